// round 1
// baseline (speedup 1.0000x reference)
#include <cuda_runtime.h>
#include <cuda_bf16.h>

// Problem: per-batch 21x21 cross-correlation, reflect padding 10.
// input: (16,3,768,768) f32   kernel: (16,21,21) f32   out: (16,3,768,768) f32
// out[b,c,h,w] = sum_{i,j} in_reflect[b,c, h+i-10, w+j-10] * ker[b,i,j]

#define BB 16
#define CC 3
#define HH 768
#define WW 768
#define KK 21
#define PP 10

#define TH 16            // output rows per CTA
#define TW 128           // output cols per CTA
#define IH (TH + KK - 1) // 36 input rows in tile
#define IW (TW + KK - 1) // 148 input cols
#define SW 152           // smem row stride (floats), mult of 4 -> float4 aligned
#define KROW 22          // kernel smem row stride

__device__ __forceinline__ int reflect_idx(int t) {
    // p=10 < H, single reflection suffices
    if (t < 0) return -t;
    if (t >= HH) return 2 * HH - 2 - t;
    return t;
}

__global__ __launch_bounds__(256, 4)
void blur_kernel(const float* __restrict__ in,
                 const float* __restrict__ ker,
                 float* __restrict__ out)
{
    __shared__ float tile[IH * SW];
    __shared__ float skern[KK * KROW];

    const int tid = threadIdx.x;
    const int bx = blockIdx.x;           // 0..5   (W tiles)
    const int by = blockIdx.y;           // 0..47  (H tiles)
    const int bz = blockIdx.z;           // 0..47  (b*3+c)
    const int b  = bz / CC;

    // ---- load per-batch kernel into smem ----
    {
        const float* kp = ker + b * (KK * KK);
        for (int idx = tid; idx < KK * KK; idx += 256) {
            skern[(idx / KK) * KROW + (idx % KK)] = kp[idx];
        }
    }

    // ---- load input halo tile with reflect indexing ----
    {
        const int gh0 = by * TH - PP;
        const int gw0 = bx * TW - PP;
        const float* img = in + (long)bz * (HH * WW);
        for (int idx = tid; idx < IH * IW; idx += 256) {
            int r = idx / IW;
            int cc = idx - r * IW;
            int gh = reflect_idx(gh0 + r);
            int gw = reflect_idx(gw0 + cc);
            tile[r * SW + cc] = img[gh * WW + gw];
        }
    }
    __syncthreads();

    // ---- compute: each thread -> 1 row x 8 cols of output ----
    const int tx = tid & 15;     // 0..15 -> 8-wide column group
    const int ty = tid >> 4;     // 0..15 -> output row within tile
    const int wc = tx * 8;       // local col of first output (16B aligned in smem)

    float acc0 = 0.f, acc1 = 0.f, acc2 = 0.f, acc3 = 0.f;
    float acc4 = 0.f, acc5 = 0.f, acc6 = 0.f, acc7 = 0.f;

    #pragma unroll 1
    for (int i = 0; i < KK; ++i) {
        // 28-float sliding window, 7 x float4 loads (16B aligned)
        const float* row = &tile[(ty + i) * SW + wc];
        float x[28];
        #pragma unroll
        for (int v = 0; v < 7; ++v) {
            float4 q = *reinterpret_cast<const float4*>(row + 4 * v);
            x[4 * v + 0] = q.x; x[4 * v + 1] = q.y;
            x[4 * v + 2] = q.z; x[4 * v + 3] = q.w;
        }
        const float* krow = &skern[i * KROW];
        #pragma unroll
        for (int j = 0; j < KK; ++j) {
            const float kv = krow[j];   // LDS broadcast
            acc0 = fmaf(x[j + 0], kv, acc0);
            acc1 = fmaf(x[j + 1], kv, acc1);
            acc2 = fmaf(x[j + 2], kv, acc2);
            acc3 = fmaf(x[j + 3], kv, acc3);
            acc4 = fmaf(x[j + 4], kv, acc4);
            acc5 = fmaf(x[j + 5], kv, acc5);
            acc6 = fmaf(x[j + 6], kv, acc6);
            acc7 = fmaf(x[j + 7], kv, acc7);
        }
    }

    // ---- write 8 outputs ----
    const int oh = by * TH + ty;
    const int ow = bx * TW + wc;
    float* op = out + (long)bz * (HH * WW) + oh * WW + ow;
    op[0] = acc0; op[1] = acc1; op[2] = acc2; op[3] = acc3;
    op[4] = acc4; op[5] = acc5; op[6] = acc6; op[7] = acc7;
}

extern "C" void kernel_launch(void* const* d_in, const int* in_sizes, int n_in,
                              void* d_out, int out_size)
{
    const float* in  = (const float*)d_in[0];   // (16,3,768,768)
    const float* ker = (const float*)d_in[1];   // (16,21,21)
    float* out = (float*)d_out;

    dim3 grid(WW / TW, HH / TH, BB * CC);       // (6, 48, 48)
    blur_kernel<<<grid, 256>>>(in, ker, out);
}

// round 2
// speedup vs baseline: 1.8560x; 1.8560x over previous
#include <cuda_runtime.h>
#include <cuda_bf16.h>

// Per-batch 21x21 cross-correlation, reflect padding 10.
// input: (16,3,768,768) f32   kernel: (16,21,21) f32   out: (16,3,768,768) f32

#define BB 16
#define CC 3
#define HH 768
#define WW 768
#define KK 21
#define PP 10

#define TH 32            // output rows per CTA (2 per thread)
#define TW 128           // output cols per CTA (8 per thread)
#define IH (TH + KK - 1) // 52 input rows in tile
#define IW (TW + KK - 1) // 148 input cols
#define SW 152           // smem row stride (floats), mult of 4 -> float4 aligned
#define KROW 24          // kernel smem row stride (padded, float4-aligned)

__device__ __forceinline__ int reflect_idx(int t) {
    if (t < 0) return -t;
    if (t >= HH) return 2 * HH - 2 - t;
    return t;
}

__global__ __launch_bounds__(256, 2)
void blur_kernel(const float* __restrict__ in,
                 const float* __restrict__ ker,
                 float* __restrict__ out)
{
    __shared__ float tile[IH * SW];        // 52*152*4 = 31616 B
    __shared__ float skern[KK * KROW];     // 21*24*4  =  2016 B

    const int tid = threadIdx.x;
    const int bx = blockIdx.x;             // 0..5   (W tiles)
    const int by = blockIdx.y;             // 0..23  (H tiles)
    const int bz = blockIdx.z;             // 0..47  (b*3+c)
    const int b  = bz / CC;

    // ---- load per-batch kernel into smem, padded to stride 24, zero pad ----
    {
        const float* kp = ker + b * (KK * KK);
        for (int idx = tid; idx < KK * KROW; idx += 256) {
            int i = idx / KROW;
            int j = idx - i * KROW;
            skern[idx] = (j < KK) ? kp[i * KK + j] : 0.f;
        }
    }

    // ---- load input halo tile with reflect indexing ----
    {
        const int gh0 = by * TH - PP;
        const int gw0 = bx * TW - PP;
        const float* img = in + (long)bz * (HH * WW);
        for (int idx = tid; idx < IH * IW; idx += 256) {
            int r  = idx / IW;
            int cc = idx - r * IW;
            int gh = reflect_idx(gh0 + r);
            int gw = reflect_idx(gw0 + cc);
            tile[r * SW + cc] = img[gh * WW + gw];
        }
    }
    __syncthreads();

    // ---- compute: each thread -> 2 rows x 8 cols of output ----
    const int tx = tid & 15;     // 0..15 -> 8-wide column group
    const int ty = tid >> 4;     // 0..15 -> output row-pair within tile
    const int wc = tx * 8;       // local col of first output (16B aligned)
    const int rb = ty * 2;       // first output row of this thread

    float a0[8], a1[8];
    #pragma unroll
    for (int c = 0; c < 8; ++c) { a0[c] = 0.f; a1[c] = 0.f; }

    float x[28];
    float wa[24], wb[24];

    // load one 28-wide input window row t (7 x float4 from smem)
    #define LOADROW(t) do {                                                   \
        const float* rp_ = &tile[(rb + (t)) * SW + wc];                       \
        _Pragma("unroll")                                                     \
        for (int v = 0; v < 7; ++v) {                                         \
            float4 q_ = *reinterpret_cast<const float4*>(rp_ + 4 * v);        \
            x[4*v] = q_.x; x[4*v+1] = q_.y; x[4*v+2] = q_.z; x[4*v+3] = q_.w; \
        }                                                                     \
    } while (0)

    // load 21 weights of kernel row t as 6 uniform float4 broadcasts
    #define LOADW(W, t) do {                                                  \
        const float* kp_ = &skern[(t) * KROW];                                \
        _Pragma("unroll")                                                     \
        for (int v = 0; v < 6; ++v) {                                         \
            float4 q_ = *reinterpret_cast<const float4*>(kp_ + 4 * v);        \
            W[4*v] = q_.x; W[4*v+1] = q_.y; W[4*v+2] = q_.z; W[4*v+3] = q_.w; \
        }                                                                     \
    } while (0)

    // A[c] += x[j+c] * W[j]  for j=0..20, c=0..7   (168 FFMA)
    #define ACC(A, W) do {                                                    \
        _Pragma("unroll")                                                     \
        for (int j = 0; j < 21; ++j) {                                        \
            const float kv_ = W[j];                                           \
            _Pragma("unroll")                                                 \
            for (int c = 0; c < 8; ++c) A[c] = fmaf(x[j + c], kv_, A[c]);     \
        }                                                                     \
    } while (0)

    // t = 0: row 0 only contributes to output row 0 (weight row 0)
    LOADW(wa, 0);
    LOADROW(0);
    ACC(a0, wa);

    // t = 1..20: row t -> acc0 with weights row t, acc1 with weights row t-1
    #pragma unroll 1
    for (int t = 1; t <= 19; t += 2) {
        LOADROW(t);     LOADW(wb, t);     ACC(a0, wb); ACC(a1, wa);
        LOADROW(t + 1); LOADW(wa, t + 1); ACC(a0, wa); ACC(a1, wb);
    }

    // t = 21: row 21 only contributes to output row 1 (weight row 20 = wa)
    LOADROW(21);
    ACC(a1, wa);

    // ---- write 2 x 8 outputs as float4 ----
    const int oh = by * TH + rb;
    const int ow = bx * TW + wc;
    float* op0 = out + (long)bz * (HH * WW) + (long)oh * WW + ow;
    float* op1 = op0 + WW;
    *reinterpret_cast<float4*>(op0)     = make_float4(a0[0], a0[1], a0[2], a0[3]);
    *reinterpret_cast<float4*>(op0 + 4) = make_float4(a0[4], a0[5], a0[6], a0[7]);
    *reinterpret_cast<float4*>(op1)     = make_float4(a1[0], a1[1], a1[2], a1[3]);
    *reinterpret_cast<float4*>(op1 + 4) = make_float4(a1[4], a1[5], a1[6], a1[7]);

    #undef LOADROW
    #undef LOADW
    #undef ACC
}

extern "C" void kernel_launch(void* const* d_in, const int* in_sizes, int n_in,
                              void* d_out, int out_size)
{
    const float* in  = (const float*)d_in[0];   // (16,3,768,768)
    const float* ker = (const float*)d_in[1];   // (16,21,21)
    float* out = (float*)d_out;

    dim3 grid(WW / TW, HH / TH, BB * CC);       // (6, 24, 48)
    blur_kernel<<<grid, 256>>>(in, ker, out);
}